// round 16
// baseline (speedup 1.0000x reference)
#include <cuda_runtime.h>
#include <math.h>

#define BD 8
#define SD 128
#define ED 50
#define DD 300
#define DED 50
#define EPSV 1e-6f

#define NODE_ELEMS (BD*SD*DD)          // 307200
#define EDGE_ELEMS (BD*SD*SD*DED)      // 6553600

#define AK 352        // padded K for combined refine GEMM (50 diag + 300 node + 2 pad)
#define WCC 128       // padded cols: 0..49 = J, 64..113 = I

// ---- scratch (no allocation allowed) ----
__device__ float g_wsum[BD*SD*SD];       // collapsed adjacency
__device__ float g_y[BD*SD*DD];          // x @ W_w
__device__ float g_A[BD*SD*AK];          // [diag | node] packed rows
__device__ float g_Wc[AK*WCC];           // combined refine weights
__device__ float g_tJ[BD*SD*DED];
__device__ float g_tI[BD*SD*DED];

#define PREP_BLOCKS 376   // ceil((AK*WCC + BD*SD*DED)/256)
#define XW_BLOCKS   192   // (BD*SD/16)*3

typedef unsigned long long ull;
__device__ __forceinline__ ull pk2(float lo, float hi) {
    ull r; asm("mov.b64 %0, {%1,%2};" : "=l"(r) : "f"(lo), "f"(hi)); return r;
}
__device__ __forceinline__ void upk2(float& lo, float& hi, ull v) {
    asm("mov.b64 {%0,%1}, %2;" : "=f"(lo), "=f"(hi) : "l"(v));
}
__device__ __forceinline__ ull fma2(ull a, ull b, ull c) {
    ull d; asm("fma.rn.f32x2 %0, %1, %2, %3;" : "=l"(d) : "l"(a), "l"(b), "l"(c)); return d;
}

// ============================================================
// k_front: three independent jobs in one launch.
//   blocks [0,1024):        Wsum[b,i,j] = mean_e softmax + (i==j)
//   blocks [1024,1400):     build g_Wc and diag part of g_A
//   blocks [1400,1592):     y = x @ W_w  (tile 16 rows x 100 cols)
// ============================================================
__global__ __launch_bounds__(256) void k_front(const float* __restrict__ wps,
                                               const float* __restrict__ wadj,
                                               const float* __restrict__ rW,
                                               const float* __restrict__ x,
                                               const float* __restrict__ Ww) {
    __shared__ __align__(16) float sm[6400];     // 25.6 KB, shared by branches
    if (blockIdx.x < 1024) {
        // ---- wsum ----
        int rbase = blockIdx.x * 128;
        const float* src = wps + (size_t)rbase * ED;
        for (int t = threadIdx.x; t < 128 * ED; t += 256) sm[t] = src[t];
        __syncthreads();
        if (threadIdx.x < 128) {
            int r = threadIdx.x;
            float s = 0.f;
            #pragma unroll
            for (int e = 0; e < ED; e++) s += sm[r * ED + e];
            int row = rbase + r;
            int j = row & 127;
            int i = (row >> 7) & 127;
            g_wsum[row] = s * (1.0f / (float)ED) + (i == j ? 1.0f : 0.0f);
        }
    } else if (blockIdx.x < 1024 + PREP_BLOCKS) {
        // ---- Wc + diag(A) prep ----
        int idx = (blockIdx.x - 1024) * 256 + threadIdx.x;
        if (idx < AK * WCC) {
            int k = idx >> 7;
            int c = idx & 127;
            float v = 0.f;
            if (k < 350) {
                if (c < DED) {
                    int row = (k < 50) ? (50 + k) : (100 + k);
                    v = rW[(size_t)row * DED + c];
                } else if (c >= 64 && c < 64 + DED) {
                    int row = (k < 50) ? (100 + k) : (400 + k);
                    v = rW[(size_t)row * DED + (c - 64)];
                }
            }
            g_Wc[idx] = v;
        } else if (idx < AK * WCC + BD * SD * DED) {
            int t = idx - AK * WCC;
            int r = t / DED, e = t % DED;
            int b = r >> 7, s = r & 127;
            g_A[(size_t)r * AK + e] = wadj[((size_t)(b * SD + s) * SD + s) * ED + e];
        }
    } else {
        // ---- xw: y = x @ W_w, tile 16 rows x 100 cols ----
        float* xsT = sm;                          // [d][r] stride 20
        int bxw = blockIdx.x - (1024 + PREP_BLOCKS);
        int rbase = (bxw / 3) * 16;
        int cbase = (bxw % 3) * 100;
        for (int t = threadIdx.x; t < 16 * DD; t += 256) {
            int r = t / DD, d = t % DD;
            xsT[d * 20 + r] = x[(size_t)(rbase + r) * DD + d];
        }
        __syncthreads();
        if (threadIdx.x >= 200) return;
        int tr = threadIdx.x / 50;     // 0..3
        int tc = threadIdx.x % 50;
        int c = cbase + tc * 2;
        float acc[4][2];
        #pragma unroll
        for (int r = 0; r < 4; r++) { acc[r][0] = 0.f; acc[r][1] = 0.f; }
        #pragma unroll 4
        for (int d = 0; d < DD; d++) {
            float4 xa = *(const float4*)&xsT[d * 20 + tr * 4];
            float2 w  = *(const float2*)&Ww[(size_t)d * DD + c];
            acc[0][0] += xa.x * w.x; acc[0][1] += xa.x * w.y;
            acc[1][0] += xa.y * w.x; acc[1][1] += xa.y * w.y;
            acc[2][0] += xa.z * w.x; acc[2][1] += xa.z * w.y;
            acc[3][0] += xa.w * w.x; acc[3][1] += xa.w * w.y;
        }
        #pragma unroll
        for (int r = 0; r < 4; r++) {
            float2 o = make_float2(acc[r][0], acc[r][1]);
            *(float2*)&g_y[(size_t)(rbase + tr * 4 + r) * DD + c] = o;
        }
    }
}

// ============================================================
// k_gemmln: h = Wsum @ y + W_b -> LayerNorm (unbiased +eps) -> ReLU
//   4 rows/block, grid 256, 320 threads (o < 300 active).
// ============================================================
__global__ __launch_bounds__(320) void k_gemmln(const float* __restrict__ Wb,
                                                const float* __restrict__ lna,
                                                const float* __restrict__ lnb,
                                                float* __restrict__ node_out) {
    __shared__ __align__(16) float wrT[SD][4];
    __shared__ float redA[10];
    __shared__ float redB[10];
    __shared__ float bc[2];
    int rb = blockIdx.x * 4;
    int b = rb >> 7;
    for (int t = threadIdx.x; t < 4 * SD; t += 320) {
        int r = t >> 7, j = t & 127;
        wrT[j][r] = g_wsum[(size_t)(rb + r) * SD + j];
    }
    __syncthreads();

    int o = threadIdx.x;
    float acc[4];
    #pragma unroll
    for (int r = 0; r < 4; r++) acc[r] = 0.f;
    if (o < DD) {
        const float* yb = g_y + (size_t)(b * SD) * DD + o;
        #pragma unroll 4
        for (int j = 0; j < SD; j++) {
            float v = yb[(size_t)j * DD];
            float4 w = *(const float4*)&wrT[j][0];
            acc[0] += w.x * v; acc[1] += w.y * v; acc[2] += w.z * v; acc[3] += w.w * v;
        }
        float bias = Wb[o];
        #pragma unroll
        for (int r = 0; r < 4; r++) acc[r] += bias;
    }
    float la = (o < DD) ? lna[o] : 0.f;
    float lb = (o < DD) ? lnb[o] : 0.f;
    int lane = threadIdx.x & 31, wid = threadIdx.x >> 5;

    for (int r = 0; r < 4; r++) {
        float h = (o < DD) ? acc[r] : 0.f;
        float s1 = h, s2 = h * h;
        #pragma unroll
        for (int off = 16; off > 0; off >>= 1) {
            s1 += __shfl_down_sync(0xffffffffu, s1, off);
            s2 += __shfl_down_sync(0xffffffffu, s2, off);
        }
        if (lane == 0) { redA[wid] = s1; redB[wid] = s2; }
        __syncthreads();
        if (threadIdx.x == 0) {
            float t1 = 0.f, t2 = 0.f;
            #pragma unroll
            for (int w = 0; w < 10; w++) { t1 += redA[w]; t2 += redB[w]; }
            bc[0] = t1; bc[1] = t2;
        }
        __syncthreads();
        float mean = bc[0] * (1.0f / (float)DD);
        float var = (bc[1] - (float)DD * mean * mean) * (1.0f / (float)(DD - 1));
        var = fmaxf(var, 0.f);
        float inv = 1.0f / (sqrtf(var) + EPSV);
        if (o < DD) {
            float nv = la * (acc[r] - mean) * inv + lb;
            nv = fmaxf(nv, 0.f);
            int gi = rb + r;
            g_A[(size_t)gi * AK + 50 + o] = nv;
            if (node_out) node_out[(size_t)gi * DD + o] = nv;
        }
        __syncthreads();
    }
}

// ============================================================
// k_terms: combined refine GEMM  [1024 x 352] @ [352 x 128] -> tJ | tI
//   grid 256, 128 thr, tile 4 rows x 128 cols, thread = 1 row x 4 cols.
// ============================================================
__global__ __launch_bounds__(128) void k_terms() {
    __shared__ __align__(16) float Ws[32][WCC];
    __shared__ float As[4][32];
    int rbase = blockIdx.x * 4;
    int r = threadIdx.x >> 5;                     // 0..3
    int lane = threadIdx.x & 31;
    int c0 = lane * 4;
    float a0 = 0.f, a1 = 0.f, a2 = 0.f, a3 = 0.f;

    for (int k0 = 0; k0 < AK; k0 += 32) {
        __syncthreads();
        #pragma unroll
        for (int p = 0; p < 8; p++) {
            int kk = r + p * 4;
            *(float4*)&Ws[kk][c0] = *(const float4*)&g_Wc[(size_t)(k0 + kk) * WCC + c0];
        }
        As[r][lane] = g_A[(size_t)(rbase + r) * AK + k0 + lane];
        __syncthreads();
        #pragma unroll
        for (int kk = 0; kk < 32; kk++) {
            float a = As[r][kk];
            float4 w = *(const float4*)&Ws[kk][c0];
            a0 += a * w.x; a1 += a * w.y; a2 += a * w.z; a3 += a * w.w;
        }
    }

    int row = rbase + r;
    if (c0 < DED) {
        float* dst = g_tJ + (size_t)row * DED + c0;
        dst[0] = a0;
        if (c0 + 1 < DED) dst[1] = a1;
        if (c0 + 2 < DED) dst[2] = a2;
        if (c0 + 3 < DED) dst[3] = a3;
    } else if (c0 >= 64 && c0 < 64 + DED) {
        int cc = c0 - 64;
        float* dst = g_tI + (size_t)row * DED + cc;
        dst[0] = a0;
        if (cc + 1 < DED) dst[1] = a1;
        if (cc + 2 < DED) dst[2] = a2;
        if (cc + 3 < DED) dst[3] = a3;
    }
}

// ============================================================
// k_edge: edge_out[row,o] = adj[row,:50]@Wa + termJ[b,j] + termI[b,i] + rb
//   Tile: 128 rows x 64 cols, 256 thr, thread = 8 rows x 4 cols.
//   Mainloop uses packed fma.rn.f32x2 (rows paired): per e
//   3 LDS128 + 8 packs + 16 FFMA2 (32 FMA).
// ============================================================
#define ATS 136   // adjT row stride in floats (16B-aligned)
__global__ __launch_bounds__(256) void k_edge(const float* __restrict__ wadj,
                                              const float* __restrict__ rW,
                                              const float* __restrict__ rb,
                                              float* __restrict__ eout) {
    __shared__ __align__(16) float adjT[ED][ATS];   // 27.2 KB, [e][row]
    __shared__ __align__(16) float WaS[ED][64];     // 12.8 KB
    __shared__ float cI[64];
    int rbase = blockIdx.x * 128;        // rows (b,i,j) with fixed (b,i)
    int b = rbase >> 14;
    int i = (rbase >> 7) & 127;

    // stage adj transposed: adjT[e][j]
    for (int t = threadIdx.x; t < 128 * ED; t += 256) {
        int row = t / ED, e = t % ED;
        adjT[e][row] = wadj[(size_t)rbase * ED + t];
    }
    // stage Wa (zero-padded to 64 cols)
    for (int t = threadIdx.x; t < ED * 64; t += 256) {
        int e = t >> 6, o = t & 63;
        WaS[e][o] = (o < DED) ? rW[(size_t)e * DED + o] : 0.f;
    }
    if (threadIdx.x < 64) {
        int o = threadIdx.x;
        cI[o] = (o < DED) ? (g_tI[(size_t)(b * SD + i) * DED + o] + rb[o]) : 0.f;
    }
    __syncthreads();

    int rg = threadIdx.x >> 4;    // 0..15 -> rows rg*8..+8
    int cg = threadIdx.x & 15;    // 0..15 -> cols cg*4..+4
    int r0 = rg * 8;
    int c0 = cg * 4;

    // acc[p][c]: row-pair p (rows r0+2p, r0+2p+1), col c0+c, packed f32x2
    ull acc[4][4];
    #pragma unroll
    for (int p = 0; p < 4; p++)
        #pragma unroll
        for (int c = 0; c < 4; c++) acc[p][c] = 0ull;

    #pragma unroll 5
    for (int e = 0; e < ED; e++) {
        float4 a0 = *(const float4*)&adjT[e][r0];
        float4 a1 = *(const float4*)&adjT[e][r0 + 4];
        float4 w  = *(const float4*)&WaS[e][c0];
        ull ap[4] = { pk2(a0.x, a0.y), pk2(a0.z, a0.w),
                      pk2(a1.x, a1.y), pk2(a1.z, a1.w) };
        ull wd[4] = { pk2(w.x, w.x), pk2(w.y, w.y),
                      pk2(w.z, w.z), pk2(w.w, w.w) };
        #pragma unroll
        for (int p = 0; p < 4; p++) {
            acc[p][0] = fma2(ap[p], wd[0], acc[p][0]);
            acc[p][1] = fma2(ap[p], wd[1], acc[p][1]);
            acc[p][2] = fma2(ap[p], wd[2], acc[p][2]);
            acc[p][3] = fma2(ap[p], wd[3], acc[p][3]);
        }
    }

    // unpack to accf[8][4]
    float accf[8][4];
    #pragma unroll
    for (int p = 0; p < 4; p++)
        #pragma unroll
        for (int c = 0; c < 4; c++)
            upk2(accf[2 * p][c], accf[2 * p + 1][c], acc[p][c]);

    // epilogue: + termJ[b,j] + (termI[b,i] + rb), float2 granularity
    if (c0 < DED) {                       // cg <= 12 active
        bool pair1_valid = (c0 + 2 < DED);  // cg=12: cols 50,51 invalid
        float2 ci0 = make_float2(cI[c0], cI[c0 + 1]);
        float2 ci1 = make_float2(cI[c0 + 2], cI[c0 + 3]);
        #pragma unroll
        for (int r = 0; r < 8; r++) {
            int j = r0 + r;
            const float2* tj2 = (const float2*)(g_tJ + (size_t)(b * SD + j) * DED + c0);
            float* orow = eout + (size_t)(rbase + j) * DED + c0;
            float2 t0 = __ldg(&tj2[0]);
            float2 o0 = make_float2(accf[r][0] + t0.x + ci0.x,
                                    accf[r][1] + t0.y + ci0.y);
            *(float2*)&orow[0] = o0;
            if (pair1_valid) {
                float2 t1 = __ldg(&tj2[1]);
                float2 o1 = make_float2(accf[r][2] + t1.x + ci1.x,
                                        accf[r][3] + t1.y + ci1.y);
                *(float2*)&orow[2] = o1;
            }
        }
    }
}

// ============================================================
extern "C" void kernel_launch(void* const* d_in, const int* in_sizes, int n_in,
                              void* d_out, int out_size) {
    const float* wps  = (const float*)d_in[0];   // [B,S,S,E]
    const float* wadj = (const float*)d_in[1];   // [B,S,S,E]
    const float* x    = (const float*)d_in[2];   // [B,S,D]
    // d_in[3] self_loop: identity by construction -> unused
    const float* Ww   = (const float*)d_in[4];   // [D,D]
    const float* Wb   = (const float*)d_in[5];   // [D]
    const float* lna  = (const float*)d_in[6];   // [D]
    const float* lnb  = (const float*)d_in[7];   // [D]
    const float* rW   = (const float*)d_in[8];   // [750,50]
    const float* rb   = (const float*)d_in[9];   // [50]

    float* out = (float*)d_out;
    float* node_out = nullptr;
    float* edge_out;
    if (out_size >= NODE_ELEMS + EDGE_ELEMS) {
        node_out = out;
        edge_out = out + NODE_ELEMS;
    } else {
        edge_out = out + (out_size - EDGE_ELEMS);  // edge-only fallback
    }

    k_front <<<1024 + PREP_BLOCKS + XW_BLOCKS, 256>>>(wps, wadj, rW, x, Ww);
    k_gemmln<<<BD*SD/4, 320>>>(Wb, lna, lnb, node_out);
    k_terms <<<BD*SD/4, 128>>>();
    k_edge  <<<BD*SD*SD/128, 256>>>(wadj, rW, rb, edge_out);
}